// round 6
// baseline (speedup 1.0000x reference)
#include <cuda_runtime.h>
#include <cuda_fp16.h>
#include <cfloat>
#include <cstdint>

#define NV 16
#define NN 8192
#define ND 256
#define NK 1024
#define W1 0.26f          // coarse-score uncertainty window (2E)
#define MARGIN 0.05f      // fp32-exact pair-adjudication margin

// ---- smem layout (bytes): A 2 bufs x (128 x 144B), B same, wsq, merge ----
#define ROWB   144
#define TILB   18432          // 128*144
#define ABUF   0
#define BBUF   36864
#define WSQ_S  73728
#define MRG    77824          // top-3 merge: 2 halves x 128 x 3 (float + int)
#define SMEM_TOTAL 83968

// ---- device scratch ----
__device__ float  g_wsq[NV * NK];
__device__ float  g_Wt[(size_t)NV * NK * ND];                    // [V][K][D] fp32
__device__ __align__(256) __half g_Xh[(size_t)NV * NN * ND];     // X fp16
__device__ __align__(256) __half g_Wh[(size_t)NV * NK * ND];     // Wt fp16
__device__ int    g_idx[NV * NN];
__device__ int    g_fix_count;
__device__ int    g_fix_rows[NV * NN];
__device__ double g_accum;

// ---- helpers ----
__device__ __forceinline__ uint32_t smem_u32(const void* p) {
    uint32_t a;
    asm("{ .reg .u64 t; cvta.to.shared.u64 t, %1; cvt.u32.u64 %0, t; }" : "=r"(a) : "l"(p));
    return a;
}
__device__ __forceinline__ void cpa16(uint32_t dst, const void* src) {
    asm volatile("cp.async.cg.shared.global [%0], [%1], 16;" :: "r"(dst), "l"(src));
}
#define CP_COMMIT() asm volatile("cp.async.commit_group;" ::: "memory")
#define CP_WAIT1()  asm volatile("cp.async.wait_group 1;" ::: "memory")
#define CP_WAIT0()  asm volatile("cp.async.wait_group 0;" ::: "memory")
__device__ __forceinline__ uint32_t lds32(uint32_t a) {
    uint32_t v; asm volatile("ld.shared.b32 %0, [%1];" : "=r"(v) : "r"(a)); return v;
}
__device__ __forceinline__ void mma16816(float* c, const uint32_t* a, const uint32_t* b) {
    asm volatile("mma.sync.aligned.m16n8k16.row.col.f32.f16.f16.f32 "
        "{%0,%1,%2,%3}, {%4,%5,%6,%7}, {%8,%9}, {%0,%1,%2,%3};"
        : "+f"(c[0]), "+f"(c[1]), "+f"(c[2]), "+f"(c[3])
        : "r"(a[0]), "r"(a[1]), "r"(a[2]), "r"(a[3]), "r"(b[0]), "r"(b[1]));
}
// sorted-triple insertion with deterministic index tiebreak
__device__ __forceinline__ void ins3(float v, int i, float* a, int* ai) {
    if (v < a[0] || (v == a[0] && i < ai[0])) {
        a[2] = a[1]; ai[2] = ai[1]; a[1] = a[0]; ai[1] = ai[0]; a[0] = v; ai[0] = i;
    } else if (v < a[1] || (v == a[1] && i < ai[1])) {
        a[2] = a[1]; ai[2] = ai[1]; a[1] = v; ai[1] = i;
    } else if (v < a[2] || (v == a[2] && i < ai[2])) {
        a[2] = v; ai[2] = i;
    }
}

// ---- prep: ||w||^2 ----
__global__ void wsq_kernel(const float* __restrict__ E) {
    int t = blockIdx.x * 256 + threadIdx.x;
    int v = t >> 10, k = t & (NK - 1);
    const float* p = E + (size_t)v * ND * NK + k;
    double s = 0.0;
    #pragma unroll 8
    for (int d = 0; d < ND; ++d) { float w = p[(size_t)d * NK]; s += (double)w * (double)w; }
    g_wsq[t] = (float)s;
    if (t == 0) { g_accum = 0.0; g_fix_count = 0; }
}

// ---- prep: transpose E [V][D][K] -> g_Wt fp32 + g_Wh fp16 (fused) ----
__global__ void transpose_kernel(const float* __restrict__ E) {
    __shared__ float t[32][33];
    int v = blockIdx.z, k0 = blockIdx.x * 32, d0 = blockIdx.y * 32;
    int tx = threadIdx.x, ty = threadIdx.y;
    const float* Ev = E + (size_t)v * ND * NK;
    #pragma unroll
    for (int j = 0; j < 32; j += 8) t[ty + j][tx] = Ev[(size_t)(d0 + ty + j) * NK + k0 + tx];
    __syncthreads();
    float* Wv = g_Wt + (size_t)v * NK * ND;
    __half* Hv = g_Wh + (size_t)v * NK * ND;
    #pragma unroll
    for (int j = 0; j < 32; j += 8) {
        float val = t[tx][ty + j];
        size_t o = (size_t)(k0 + ty + j) * ND + d0 + tx;
        Wv[o] = val;
        Hv[o] = __float2half_rn(val);
    }
}

__global__ void convertX_kernel(const float* __restrict__ X) {
    size_t i2 = ((size_t)blockIdx.x * 256 + threadIdx.x) * 2;
    float2 x = *(const float2*)(X + i2);
    *(__half2*)(&g_Xh[i2]) = __floats2half2_rn(x.x, x.y);
}

// ---- exact fp64 score ----
__device__ double dscore(const float* __restrict__ xrow, const float* __restrict__ Ev, int k) {
    const float* wc = Ev + k;
    double dot = 0.0, ws = 0.0;
    #pragma unroll 4
    for (int d = 0; d < ND; ++d) {
        double w = (double)wc[(size_t)d * NK];
        dot += (double)xrow[d] * w;
        ws  += w * w;
    }
    return ws - 2.0 * dot;
}

// ---- main: single-plane fp16 HMMA + top-3 + windowed adjudication ----
// grid (NN/128, NV), 256 thr = 8 warps (4M x 2N), warp tile 32x64, occupancy 1 (no spills)
__global__ void __launch_bounds__(256, 1)
gemm_argmin_kernel(const float* __restrict__ X, const float* __restrict__ E) {
    extern __shared__ char smem[];
    const uint32_t sb = smem_u32(smem);
    const int tid = threadIdx.x, lane = tid & 31, wid = tid >> 5;
    const int wm = wid & 3, wn = wid >> 2;
    const int g = lane >> 2, tg = lane & 3;
    const int v = blockIdx.y, row0 = blockIdx.x * 128;

    {
        float* sw = (float*)(smem + WSQ_S);
        #pragma unroll
        for (int q = 0; q < 4; ++q) sw[tid + q * 256] = g_wsq[v * NK + tid + q * 256];
    }

    auto issue = [&](int it) {
        int nc = it >> 2, dc = it & 3, buf = it & 1;
        size_t abase = ((size_t)v * NN + row0) * ND + dc * 64;
        size_t bbase = ((size_t)v * NK + nc * 128) * ND + dc * 64;
        #pragma unroll
        for (int j = 0; j < 4; ++j) {
            int q = tid * 4 + j;                // 0..1023 16B-chunks
            int r = q >> 3, c = q & 7;
            cpa16(sb + ABUF + buf * TILB + r * ROWB + c * 16,
                  (const char*)g_Xh + (abase + (size_t)r * ND) * 2 + c * 16);
            cpa16(sb + BBUF + buf * TILB + r * ROWB + c * 16,
                  (const char*)g_Wh + (bbase + (size_t)r * ND) * 2 + c * 16);
        }
        CP_COMMIT();
    };

    // per-thread top-3 per row-slot (4 slots)
    float tv[4][3]; int ti[4][3];
    #pragma unroll
    for (int s = 0; s < 4; ++s)
        #pragma unroll
        for (int j = 0; j < 3; ++j) { tv[s][j] = FLT_MAX; ti[s][j] = 0x7FFFFFFF; }

    issue(0);
    const float* sw = (const float*)(smem + WSQ_S);

    for (int nc = 0; nc < 8; ++nc) {
        float c[2][8][4];
        #pragma unroll
        for (int mf = 0; mf < 2; ++mf)
            #pragma unroll
            for (int nf = 0; nf < 8; ++nf)
                #pragma unroll
                for (int e = 0; e < 4; ++e) c[mf][nf][e] = 0.0f;

        for (int dc = 0; dc < 4; ++dc) {
            int it = nc * 4 + dc, buf = it & 1;
            if (it < 31) { issue(it + 1); CP_WAIT1(); } else { CP_WAIT0(); }
            __syncthreads();

            const uint32_t Ab = sb + ABUF + buf * TILB;
            const uint32_t Bb = sb + BBUF + buf * TILB;
            #pragma unroll
            for (int ks = 0; ks < 4; ++ks) {
                const uint32_t kb = ks * 32 + tg * 4;
                uint32_t A[2][4];
                #pragma unroll
                for (int mf = 0; mf < 2; ++mf) {
                    uint32_t ra = Ab + (wm * 32 + mf * 16 + g) * ROWB + kb;
                    A[mf][0] = lds32(ra);       A[mf][1] = lds32(ra + 8 * ROWB);
                    A[mf][2] = lds32(ra + 16);  A[mf][3] = lds32(ra + 8 * ROWB + 16);
                }
                uint32_t B[8][2];
                #pragma unroll
                for (int nf = 0; nf < 8; ++nf) {
                    uint32_t rb = Bb + (wn * 64 + nf * 8 + g) * ROWB + kb;
                    B[nf][0] = lds32(rb); B[nf][1] = lds32(rb + 16);
                }
                #pragma unroll
                for (int mf = 0; mf < 2; ++mf)
                    #pragma unroll
                    for (int nf = 0; nf < 8; ++nf) mma16816(c[mf][nf], A[mf], B[nf]);
            }
            __syncthreads();
        }

        #pragma unroll
        for (int mf = 0; mf < 2; ++mf)
            #pragma unroll
            for (int nf = 0; nf < 8; ++nf)
                #pragma unroll
                for (int e = 0; e < 4; ++e) {
                    int col  = nc * 128 + wn * 64 + nf * 8 + tg * 2 + (e & 1);
                    int slot = mf * 2 + (e >> 1);
                    float sc = sw[col] - 2.0f * c[mf][nf][e];
                    float* a = tv[slot]; int* ai = ti[slot];
                    if (sc < a[2]) {
                        if (sc < a[1]) {
                            a[2] = a[1]; ai[2] = ai[1];
                            if (sc < a[0]) { a[1] = a[0]; ai[1] = ai[0]; a[0] = sc; ai[0] = col; }
                            else           { a[1] = sc; ai[1] = col; }
                        } else { a[2] = sc; ai[2] = col; }
                    }
                }
    }

    // merge top-3 across the 4 lanes sharing each row
    const unsigned m = 0xFFFFFFFFu;
    #pragma unroll
    for (int off = 1; off < 4; off <<= 1) {
        #pragma unroll
        for (int s = 0; s < 4; ++s) {
            float ov[3]; int oi[3];
            #pragma unroll
            for (int j = 0; j < 3; ++j) {
                ov[j] = __shfl_xor_sync(m, tv[s][j], off);
                oi[j] = __shfl_xor_sync(m, ti[s][j], off);
            }
            #pragma unroll
            for (int j = 0; j < 3; ++j) ins3(ov[j], oi[j], tv[s], ti[s]);
        }
    }

    float* mv = (float*)(smem + MRG);          // [2][128][3]
    int*   mi = (int*)  (smem + MRG + 3072);
    if (tg == 0) {
        #pragma unroll
        for (int s = 0; s < 4; ++s) {
            int rl = wm * 32 + (s >> 1) * 16 + g + (s & 1) * 8;
            #pragma unroll
            for (int j = 0; j < 3; ++j) {
                mv[(wn * 128 + rl) * 3 + j] = tv[s][j];
                mi[(wn * 128 + rl) * 3 + j] = ti[s][j];
            }
        }
    }
    __syncthreads();

    if (tid < 128) {
        float a[3]; int ai[3];
        #pragma unroll
        for (int j = 0; j < 3; ++j) { a[j] = mv[tid * 3 + j]; ai[j] = mi[tid * 3 + j]; }
        #pragma unroll
        for (int j = 0; j < 3; ++j) ins3(mv[(128 + tid) * 3 + j], mi[(128 + tid) * 3 + j], a, ai);

        int grow = row0 + tid, kk = ai[0];
        float gap2 = a[1] - a[0], gap3 = a[2] - a[0];
        if (gap3 < W1) {
            int slot = atomicAdd(&g_fix_count, 1);
            g_fix_rows[slot] = v * NN + grow;          // full exact rescore later
        } else if (gap2 < W1) {
            const float* xrow = X + ((size_t)v * NN + grow) * ND;
            const float* Ev = E + (size_t)v * ND * NK;
            double sb2 = dscore(xrow, Ev, ai[0]);
            double ss2 = dscore(xrow, Ev, ai[1]);
            if (ss2 < sb2 || (ss2 == sb2 && ai[1] < ai[0])) kk = ai[1];
        }
        g_idx[v * NN + grow] = kk;
    }
}

// ---- exact full-row rescore for flagged rows (one block per row) ----
__global__ void __launch_bounds__(256)
fix_kernel(const float* __restrict__ X, const float* __restrict__ E) {
    __shared__ float xs[ND];
    __shared__ float wv[16];
    __shared__ int   wi[16];
    int cnt = g_fix_count;
    for (int f = blockIdx.x; f < cnt; f += gridDim.x) {
        int R = g_fix_rows[f];
        int v = R >> 13;
        __syncthreads();
        xs[threadIdx.x] = X[(size_t)R * ND + threadIdx.x];
        __syncthreads();

        float b = FLT_MAX, s = FLT_MAX; int bi = 0x7FFFFFFF, si = 0x7FFFFFFF;
        #pragma unroll
        for (int kk = 0; kk < 4; ++kk) {
            int k = threadIdx.x * 4 + kk;
            const float* w = g_Wt + ((size_t)v * NK + k) * ND;
            float dot = 0.0f;
            #pragma unroll 8
            for (int d = 0; d < ND; ++d) dot = fmaf(xs[d], w[d], dot);
            float sc = g_wsq[v * NK + k] - 2.0f * dot;
            if (sc < b || (sc == b && k < bi)) { s = b; si = bi; b = sc; bi = k; }
            else if (sc < s || (sc == s && k < si)) { s = sc; si = k; }
        }
        const unsigned m = 0xFFFFFFFFu;
        #pragma unroll
        for (int off = 1; off < 32; off <<= 1) {
            float ob = __shfl_xor_sync(m, b, off);  int obi = __shfl_xor_sync(m, bi, off);
            float os = __shfl_xor_sync(m, s, off);  int osi = __shfl_xor_sync(m, si, off);
            bool tko = (ob < b) || (ob == b && obi < bi);
            float lb = tko ? b : ob; int lbi = tko ? bi : obi;
            float ws_ = tko ? os : s; int wsi = tko ? osi : si;
            if (tko) { b = ob; bi = obi; }
            if (ws_ < lb || (ws_ == lb && wsi < lbi)) { s = ws_; si = wsi; }
            else                                      { s = lb;  si = lbi; }
        }
        int wrp = threadIdx.x >> 5;
        if ((threadIdx.x & 31) == 0) { wv[wrp * 2] = b; wv[wrp * 2 + 1] = s; wi[wrp * 2] = bi; wi[wrp * 2 + 1] = si; }
        __syncthreads();
        if (threadIdx.x == 0) {
            float B = FLT_MAX, S = FLT_MAX; int Bi = 0x7FFFFFFF, Si = 0x7FFFFFFF;
            for (int q = 0; q < 16; ++q) {
                float vq = wv[q]; int iq = wi[q];
                if (vq < B || (vq == B && iq < Bi)) { S = B; Si = Bi; B = vq; Bi = iq; }
                else if (vq < S || (vq == S && iq < Si)) { S = vq; Si = iq; }
            }
            int kk = Bi;
            if (S - B < MARGIN) {
                const float* Ev = E + (size_t)v * ND * NK;
                double sb2 = dscore(xs, Ev, Bi);
                double ss2 = dscore(xs, Ev, Si);
                if (ss2 < sb2 || (ss2 == sb2 && Si < Bi)) kk = Si;
            }
            g_idx[R] = kk;
        }
        __syncthreads();
    }
}

// ---- gather + loss ----
__global__ void __launch_bounds__(256)
gather_kernel(const float* __restrict__ X, float* __restrict__ out) {
    int R = blockIdx.x * 4 + (threadIdx.x >> 6);
    int lane64 = threadIdx.x & 63;
    int k = g_idx[R];
    int v = R >> 13;
    float4 qv = ((const float4*)(g_Wt + ((size_t)v * NK + k) * ND))[lane64];
    float4 xv = ((const float4*)(X + (size_t)R * ND))[lane64];
    ((float4*)(out + (size_t)R * ND))[lane64] = qv;

    float dx = qv.x - xv.x, dy = qv.y - xv.y, dz = qv.z - xv.z, dw = qv.w - xv.w;
    float s = dx * dx + dy * dy + dz * dz + dw * dw;
    #pragma unroll
    for (int off = 16; off > 0; off >>= 1) s += __shfl_down_sync(0xFFFFFFFFu, s, off);

    __shared__ float ps[8];
    int w = threadIdx.x >> 5, l = threadIdx.x & 31;
    if (l == 0) ps[w] = s;
    __syncthreads();
    if (threadIdx.x == 0) {
        float tot = 0.0f;
        #pragma unroll
        for (int i = 0; i < 8; ++i) tot += ps[i];
        atomicAdd(&g_accum, (double)tot);
    }
}

__global__ void loss_kernel(float* __restrict__ out, long long out_size) {
    const long long VND = (long long)NV * NN * ND;
    double loss = 1.25 * g_accum / (double)VND;
    for (long long i = VND + threadIdx.x; i < out_size; i += blockDim.x)
        out[i] = (float)loss;
}

extern "C" void kernel_launch(void* const* d_in, const int* in_sizes, int n_in,
                              void* d_out, int out_size) {
    const float* X = (const float*)d_in[0];
    const float* E = (const float*)d_in[1];
    float* out = (float*)d_out;

    cudaFuncSetAttribute((const void*)gemm_argmin_kernel,
                         cudaFuncAttributeMaxDynamicSharedMemorySize, SMEM_TOTAL);

    wsq_kernel<<<64, 256>>>(E);
    transpose_kernel<<<dim3(NK / 32, ND / 32, NV), dim3(32, 8)>>>(E);
    convertX_kernel<<<65536, 256>>>(X);
    gemm_argmin_kernel<<<dim3(NN / 128, NV), 256, SMEM_TOTAL>>>(X, E);
    fix_kernel<<<1024, 256>>>(X, E);
    gather_kernel<<<(NV * NN) / 4, 256>>>(X, out);
    loss_kernel<<<1, 32>>>(out, (long long)out_size);
}

// round 7
// speedup vs baseline: 1.0528x; 1.0528x over previous
#include <cuda_runtime.h>
#include <cuda_fp16.h>
#include <cfloat>
#include <cstdint>

#define NV 16
#define NN 8192
#define ND 256
#define NK 1024
#define W1 0.26f          // coarse-score uncertainty window
#define MARGIN 0.05f      // fp32-exact pair-adjudication margin

// ---- smem layout (bytes): A 2 bufs x (128 x 144B), B same, wsq, merge ----
#define ROWB   144
#define TILB   18432          // 128*144
#define ABUF   0
#define BBUF   36864
#define WSQ_S  73728
#define MRG    77824          // top-3 merge: 4 n-groups x 128 x 3 (float + int) = 12288
#define SMEM_TOTAL 90112

// ---- device scratch ----
__device__ float  g_wsq[NV * NK];
__device__ float  g_Wt[(size_t)NV * NK * ND];                    // [V][K][D] fp32
__device__ __align__(256) __half g_Xh[(size_t)NV * NN * ND];     // X fp16
__device__ __align__(256) __half g_Wh[(size_t)NV * NK * ND];     // Wt fp16
__device__ int    g_idx[NV * NN];
__device__ int    g_fix_count;
__device__ int    g_fix_rows[NV * NN];
__device__ double g_accum;

// ---- helpers ----
__device__ __forceinline__ uint32_t smem_u32(const void* p) {
    uint32_t a;
    asm("{ .reg .u64 t; cvta.to.shared.u64 t, %1; cvt.u32.u64 %0, t; }" : "=r"(a) : "l"(p));
    return a;
}
__device__ __forceinline__ void cpa16(uint32_t dst, const void* src) {
    asm volatile("cp.async.cg.shared.global [%0], [%1], 16;" :: "r"(dst), "l"(src));
}
#define CP_COMMIT() asm volatile("cp.async.commit_group;" ::: "memory")
#define CP_WAIT1()  asm volatile("cp.async.wait_group 1;" ::: "memory")
#define CP_WAIT0()  asm volatile("cp.async.wait_group 0;" ::: "memory")
__device__ __forceinline__ uint32_t lds32(uint32_t a) {
    uint32_t v; asm volatile("ld.shared.b32 %0, [%1];" : "=r"(v) : "r"(a)); return v;
}
__device__ __forceinline__ void mma16816(float* c, const uint32_t* a, const uint32_t* b) {
    asm volatile("mma.sync.aligned.m16n8k16.row.col.f32.f16.f16.f32 "
        "{%0,%1,%2,%3}, {%4,%5,%6,%7}, {%8,%9}, {%0,%1,%2,%3};"
        : "+f"(c[0]), "+f"(c[1]), "+f"(c[2]), "+f"(c[3])
        : "r"(a[0]), "r"(a[1]), "r"(a[2]), "r"(a[3]), "r"(b[0]), "r"(b[1]));
}
__device__ __forceinline__ void ins3(float v, int i, float* a, int* ai) {
    if (v < a[0] || (v == a[0] && i < ai[0])) {
        a[2] = a[1]; ai[2] = ai[1]; a[1] = a[0]; ai[1] = ai[0]; a[0] = v; ai[0] = i;
    } else if (v < a[1] || (v == a[1] && i < ai[1])) {
        a[2] = a[1]; ai[2] = ai[1]; a[1] = v; ai[1] = i;
    } else if (v < a[2] || (v == a[2] && i < ai[2])) {
        a[2] = v; ai[2] = i;
    }
}

// ---- prep: ||w||^2 ----
__global__ void wsq_kernel(const float* __restrict__ E) {
    int t = blockIdx.x * 256 + threadIdx.x;
    int v = t >> 10, k = t & (NK - 1);
    const float* p = E + (size_t)v * ND * NK + k;
    double s = 0.0;
    #pragma unroll 8
    for (int d = 0; d < ND; ++d) { float w = p[(size_t)d * NK]; s += (double)w * (double)w; }
    g_wsq[t] = (float)s;
    if (t == 0) { g_accum = 0.0; g_fix_count = 0; }
}

// ---- prep: transpose E -> g_Wt fp32 + g_Wh fp16 (fused) ----
__global__ void transpose_kernel(const float* __restrict__ E) {
    __shared__ float t[32][33];
    int v = blockIdx.z, k0 = blockIdx.x * 32, d0 = blockIdx.y * 32;
    int tx = threadIdx.x, ty = threadIdx.y;
    const float* Ev = E + (size_t)v * ND * NK;
    #pragma unroll
    for (int j = 0; j < 32; j += 8) t[ty + j][tx] = Ev[(size_t)(d0 + ty + j) * NK + k0 + tx];
    __syncthreads();
    float* Wv = g_Wt + (size_t)v * NK * ND;
    __half* Hv = g_Wh + (size_t)v * NK * ND;
    #pragma unroll
    for (int j = 0; j < 32; j += 8) {
        float val = t[tx][ty + j];
        size_t o = (size_t)(k0 + ty + j) * ND + d0 + tx;
        Wv[o] = val;
        Hv[o] = __float2half_rn(val);
    }
}

__global__ void convertX_kernel(const float* __restrict__ X) {
    size_t i2 = ((size_t)blockIdx.x * 256 + threadIdx.x) * 2;
    float2 x = *(const float2*)(X + i2);
    *(__half2*)(&g_Xh[i2]) = __floats2half2_rn(x.x, x.y);
}

// ---- exact fp64 score ----
__device__ double dscore(const float* __restrict__ xrow, const float* __restrict__ Ev, int k) {
    const float* wc = Ev + k;
    double dot = 0.0, ws = 0.0;
    #pragma unroll 4
    for (int d = 0; d < ND; ++d) {
        double w = (double)wc[(size_t)d * NK];
        dot += (double)xrow[d] * w;
        ws  += w * w;
    }
    return ws - 2.0 * dot;
}

// ---- main: fp16 HMMA + top-3 + windowed adjudication ----
// grid (NN/128, NV), 512 thr = 16 warps (4M x 4N), warp tile 32x32
__global__ void __launch_bounds__(512, 1)
gemm_argmin_kernel(const float* __restrict__ X, const float* __restrict__ E) {
    extern __shared__ char smem[];
    const uint32_t sb = smem_u32(smem);
    const int tid = threadIdx.x, lane = tid & 31, wid = tid >> 5;
    const int wm = wid & 3, wn = wid >> 2;        // 4M x 4N
    const int g = lane >> 2, tg = lane & 3;
    const int v = blockIdx.y, row0 = blockIdx.x * 128;

    {
        float* sw = (float*)(smem + WSQ_S);
        #pragma unroll
        for (int q = 0; q < 2; ++q) sw[tid + q * 512] = g_wsq[v * NK + tid + q * 512];
    }

    auto issue = [&](int it) {
        int nc = it >> 2, dc = it & 3, buf = it & 1;
        size_t abase = ((size_t)v * NN + row0) * ND + dc * 64;
        size_t bbase = ((size_t)v * NK + nc * 128) * ND + dc * 64;
        #pragma unroll
        for (int j = 0; j < 2; ++j) {
            int q = tid * 2 + j;                // 0..1023 16B-chunks
            int r = q >> 3, c = q & 7;
            cpa16(sb + ABUF + buf * TILB + r * ROWB + c * 16,
                  (const char*)g_Xh + (abase + (size_t)r * ND) * 2 + c * 16);
            cpa16(sb + BBUF + buf * TILB + r * ROWB + c * 16,
                  (const char*)g_Wh + (bbase + (size_t)r * ND) * 2 + c * 16);
        }
        CP_COMMIT();
    };

    // per-thread top-3 per row-slot (4 slots: mf*2 + half)
    float tv[4][3]; int ti[4][3];
    #pragma unroll
    for (int s = 0; s < 4; ++s)
        #pragma unroll
        for (int j = 0; j < 3; ++j) { tv[s][j] = FLT_MAX; ti[s][j] = 0x7FFFFFFF; }

    issue(0);
    const float* sw = (const float*)(smem + WSQ_S);

    for (int nc = 0; nc < 8; ++nc) {
        float c[2][4][4];
        #pragma unroll
        for (int mf = 0; mf < 2; ++mf)
            #pragma unroll
            for (int nf = 0; nf < 4; ++nf)
                #pragma unroll
                for (int e = 0; e < 4; ++e) c[mf][nf][e] = 0.0f;

        for (int dc = 0; dc < 4; ++dc) {
            int it = nc * 4 + dc, buf = it & 1;
            if (it < 31) { issue(it + 1); CP_WAIT1(); } else { CP_WAIT0(); }
            __syncthreads();

            const uint32_t Ab = sb + ABUF + buf * TILB;
            const uint32_t Bb = sb + BBUF + buf * TILB;
            #pragma unroll
            for (int ks = 0; ks < 4; ++ks) {
                const uint32_t kb = ks * 32 + tg * 4;
                uint32_t A[2][4];
                #pragma unroll
                for (int mf = 0; mf < 2; ++mf) {
                    uint32_t ra = Ab + (wm * 32 + mf * 16 + g) * ROWB + kb;
                    A[mf][0] = lds32(ra);       A[mf][1] = lds32(ra + 8 * ROWB);
                    A[mf][2] = lds32(ra + 16);  A[mf][3] = lds32(ra + 8 * ROWB + 16);
                }
                uint32_t B[4][2];
                #pragma unroll
                for (int nf = 0; nf < 4; ++nf) {
                    uint32_t rb = Bb + (wn * 32 + nf * 8 + g) * ROWB + kb;
                    B[nf][0] = lds32(rb); B[nf][1] = lds32(rb + 16);
                }
                #pragma unroll
                for (int mf = 0; mf < 2; ++mf)
                    #pragma unroll
                    for (int nf = 0; nf < 4; ++nf) mma16816(c[mf][nf], A[mf], B[nf]);
            }
            __syncthreads();
        }

        #pragma unroll
        for (int mf = 0; mf < 2; ++mf)
            #pragma unroll
            for (int nf = 0; nf < 4; ++nf)
                #pragma unroll
                for (int e = 0; e < 4; ++e) {
                    int col  = nc * 128 + wn * 32 + nf * 8 + tg * 2 + (e & 1);
                    int slot = mf * 2 + (e >> 1);
                    float sc = sw[col] - 2.0f * c[mf][nf][e];
                    float* a = tv[slot]; int* ai = ti[slot];
                    if (sc < a[2]) {
                        if (sc < a[1]) {
                            a[2] = a[1]; ai[2] = ai[1];
                            if (sc < a[0]) { a[1] = a[0]; ai[1] = ai[0]; a[0] = sc; ai[0] = col; }
                            else           { a[1] = sc; ai[1] = col; }
                        } else { a[2] = sc; ai[2] = col; }
                    }
                }
    }

    // merge top-3 across the 4 lanes sharing each row
    const unsigned m = 0xFFFFFFFFu;
    #pragma unroll
    for (int off = 1; off < 4; off <<= 1) {
        #pragma unroll
        for (int s = 0; s < 4; ++s) {
            float ov[3]; int oi[3];
            #pragma unroll
            for (int j = 0; j < 3; ++j) {
                ov[j] = __shfl_xor_sync(m, tv[s][j], off);
                oi[j] = __shfl_xor_sync(m, ti[s][j], off);
            }
            #pragma unroll
            for (int j = 0; j < 3; ++j) ins3(ov[j], oi[j], tv[s], ti[s]);
        }
    }

    float* mv = (float*)(smem + MRG);          // [4][128][3]
    int*   mi = (int*)  (smem + MRG + 6144);
    if (tg == 0) {
        #pragma unroll
        for (int s = 0; s < 4; ++s) {
            int rl = wm * 32 + (s >> 1) * 16 + g + (s & 1) * 8;
            #pragma unroll
            for (int j = 0; j < 3; ++j) {
                mv[(wn * 128 + rl) * 3 + j] = tv[s][j];
                mi[(wn * 128 + rl) * 3 + j] = ti[s][j];
            }
        }
    }
    __syncthreads();

    if (tid < 128) {
        float a[3]; int ai[3];
        #pragma unroll
        for (int j = 0; j < 3; ++j) { a[j] = mv[tid * 3 + j]; ai[j] = mi[tid * 3 + j]; }
        #pragma unroll
        for (int grp = 1; grp < 4; ++grp)
            #pragma unroll
            for (int j = 0; j < 3; ++j)
                ins3(mv[(grp * 128 + tid) * 3 + j], mi[(grp * 128 + tid) * 3 + j], a, ai);

        int grow = row0 + tid, kk = ai[0];
        float gap2 = a[1] - a[0], gap3 = a[2] - a[0];
        if (gap3 < W1) {
            int slot = atomicAdd(&g_fix_count, 1);
            g_fix_rows[slot] = v * NN + grow;          // full exact rescore later
        } else if (gap2 < W1) {
            const float* xrow = X + ((size_t)v * NN + grow) * ND;
            const float* Ev = E + (size_t)v * ND * NK;
            double sb2 = dscore(xrow, Ev, ai[0]);
            double ss2 = dscore(xrow, Ev, ai[1]);
            if (ss2 < sb2 || (ss2 == sb2 && ai[1] < ai[0])) kk = ai[1];
        }
        g_idx[v * NN + grow] = kk;
    }
}

// ---- exact full-row rescore for flagged rows ----
__global__ void __launch_bounds__(256)
fix_kernel(const float* __restrict__ X, const float* __restrict__ E) {
    __shared__ float xs[ND];
    __shared__ float wv[16];
    __shared__ int   wi[16];
    int cnt = g_fix_count;
    for (int f = blockIdx.x; f < cnt; f += gridDim.x) {
        int R = g_fix_rows[f];
        int v = R >> 13;
        __syncthreads();
        xs[threadIdx.x] = X[(size_t)R * ND + threadIdx.x];
        __syncthreads();

        float b = FLT_MAX, s = FLT_MAX; int bi = 0x7FFFFFFF, si = 0x7FFFFFFF;
        #pragma unroll
        for (int kk = 0; kk < 4; ++kk) {
            int k = threadIdx.x * 4 + kk;
            const float* w = g_Wt + ((size_t)v * NK + k) * ND;
            float dot = 0.0f;
            #pragma unroll 8
            for (int d = 0; d < ND; ++d) dot = fmaf(xs[d], w[d], dot);
            float sc = g_wsq[v * NK + k] - 2.0f * dot;
            if (sc < b || (sc == b && k < bi)) { s = b; si = bi; b = sc; bi = k; }
            else if (sc < s || (sc == s && k < si)) { s = sc; si = k; }
        }
        const unsigned m = 0xFFFFFFFFu;
        #pragma unroll
        for (int off = 1; off < 32; off <<= 1) {
            float ob = __shfl_xor_sync(m, b, off);  int obi = __shfl_xor_sync(m, bi, off);
            float os = __shfl_xor_sync(m, s, off);  int osi = __shfl_xor_sync(m, si, off);
            bool tko = (ob < b) || (ob == b && obi < bi);
            float lb = tko ? b : ob; int lbi = tko ? bi : obi;
            float ws_ = tko ? os : s; int wsi = tko ? osi : si;
            if (tko) { b = ob; bi = obi; }
            if (ws_ < lb || (ws_ == lb && wsi < lbi)) { s = ws_; si = wsi; }
            else                                      { s = lb;  si = lbi; }
        }
        int wrp = threadIdx.x >> 5;
        if ((threadIdx.x & 31) == 0) { wv[wrp * 2] = b; wv[wrp * 2 + 1] = s; wi[wrp * 2] = bi; wi[wrp * 2 + 1] = si; }
        __syncthreads();
        if (threadIdx.x == 0) {
            float B = FLT_MAX, S = FLT_MAX; int Bi = 0x7FFFFFFF, Si = 0x7FFFFFFF;
            for (int q = 0; q < 16; ++q) {
                float vq = wv[q]; int iq = wi[q];
                if (vq < B || (vq == B && iq < Bi)) { S = B; Si = Bi; B = vq; Bi = iq; }
                else if (vq < S || (vq == S && iq < Si)) { S = vq; Si = iq; }
            }
            int kk = Bi;
            if (S - B < MARGIN) {
                const float* Ev = E + (size_t)v * ND * NK;
                double sb2 = dscore(xs, Ev, Bi);
                double ss2 = dscore(xs, Ev, Si);
                if (ss2 < sb2 || (ss2 == sb2 && Si < Bi)) kk = Si;
            }
            g_idx[R] = kk;
        }
        __syncthreads();
    }
}

// ---- gather + loss ----
__global__ void __launch_bounds__(256)
gather_kernel(const float* __restrict__ X, float* __restrict__ out) {
    int R = blockIdx.x * 4 + (threadIdx.x >> 6);
    int lane64 = threadIdx.x & 63;
    int k = g_idx[R];
    int v = R >> 13;
    float4 qv = ((const float4*)(g_Wt + ((size_t)v * NK + k) * ND))[lane64];
    float4 xv = ((const float4*)(X + (size_t)R * ND))[lane64];
    ((float4*)(out + (size_t)R * ND))[lane64] = qv;

    float dx = qv.x - xv.x, dy = qv.y - xv.y, dz = qv.z - xv.z, dw = qv.w - xv.w;
    float s = dx * dx + dy * dy + dz * dz + dw * dw;
    #pragma unroll
    for (int off = 16; off > 0; off >>= 1) s += __shfl_down_sync(0xFFFFFFFFu, s, off);

    __shared__ float ps[8];
    int w = threadIdx.x >> 5, l = threadIdx.x & 31;
    if (l == 0) ps[w] = s;
    __syncthreads();
    if (threadIdx.x == 0) {
        float tot = 0.0f;
        #pragma unroll
        for (int i = 0; i < 8; ++i) tot += ps[i];
        atomicAdd(&g_accum, (double)tot);
    }
}

__global__ void loss_kernel(float* __restrict__ out, long long out_size) {
    const long long VND = (long long)NV * NN * ND;
    double loss = 1.25 * g_accum / (double)VND;
    for (long long i = VND + threadIdx.x; i < out_size; i += blockDim.x)
        out[i] = (float)loss;
}

extern "C" void kernel_launch(void* const* d_in, const int* in_sizes, int n_in,
                              void* d_out, int out_size) {
    const float* X = (const float*)d_in[0];
    const float* E = (const float*)d_in[1];
    float* out = (float*)d_out;

    cudaFuncSetAttribute((const void*)gemm_argmin_kernel,
                         cudaFuncAttributeMaxDynamicSharedMemorySize, SMEM_TOTAL);

    wsq_kernel<<<64, 256>>>(E);
    transpose_kernel<<<dim3(NK / 32, ND / 32, NV), dim3(32, 8)>>>(E);
    convertX_kernel<<<65536, 256>>>(X);
    gemm_argmin_kernel<<<dim3(NN / 128, NV), 512, SMEM_TOTAL>>>(X, E);
    fix_kernel<<<1024, 256>>>(X, E);
    gather_kernel<<<(NV * NN) / 4, 256>>>(X, out);
    loss_kernel<<<1, 32>>>(out, (long long)out_size);
}

// round 8
// speedup vs baseline: 1.4061x; 1.3356x over previous
#include <cuda_runtime.h>
#include <cuda_fp16.h>
#include <cfloat>
#include <cstdint>

#define NV 16
#define NN 8192
#define ND 256
#define NK 1024
#define W1 0.26f          // coarse-score uncertainty window
#define MARGIN 0.05f      // fp32-exact pair-adjudication margin

// ---- smem layout (bytes) ----
// A resident: 4 tiles x (128 rows x 144B) = 73728
// B ring:     3 bufs  x (64 rows x 144B)  = 27648
#define ROWB   144
#define ATILB  18432
#define BTILB  9216
#define AOFF   0
#define BOFF   73728
#define WSQ_S  101376
#define MRG    105472         // 2 n-groups x 128 x 3 x (4+4)B = 6144
#define SMEM_TOTAL 111616

// ---- device scratch ----
__device__ float  g_wsq[NV * NK];
__device__ float  g_Wt[(size_t)NV * NK * ND];                    // [V][K][D] fp32
__device__ __align__(256) __half g_Xh[(size_t)NV * NN * ND];     // X fp16
__device__ __align__(256) __half g_Wh[(size_t)NV * NK * ND];     // Wt fp16
__device__ int    g_idx[NV * NN];
__device__ int    g_fix_count;
__device__ int    g_fix_rows[NV * NN];
__device__ double g_accum;

// ---- helpers ----
__device__ __forceinline__ uint32_t smem_u32(const void* p) {
    uint32_t a;
    asm("{ .reg .u64 t; cvta.to.shared.u64 t, %1; cvt.u32.u64 %0, t; }" : "=r"(a) : "l"(p));
    return a;
}
__device__ __forceinline__ void cpa16(uint32_t dst, const void* src) {
    asm volatile("cp.async.cg.shared.global [%0], [%1], 16;" :: "r"(dst), "l"(src));
}
#define CP_COMMIT() asm volatile("cp.async.commit_group;" ::: "memory")
#define CP_WAIT1()  asm volatile("cp.async.wait_group 1;" ::: "memory")
#define CP_WAIT0()  asm volatile("cp.async.wait_group 0;" ::: "memory")
__device__ __forceinline__ uint32_t lds32(uint32_t a) {
    uint32_t v; asm volatile("ld.shared.b32 %0, [%1];" : "=r"(v) : "r"(a)); return v;
}
__device__ __forceinline__ void mma16816(float* c, const uint32_t* a, const uint32_t* b) {
    asm volatile("mma.sync.aligned.m16n8k16.row.col.f32.f16.f16.f32 "
        "{%0,%1,%2,%3}, {%4,%5,%6,%7}, {%8,%9}, {%0,%1,%2,%3};"
        : "+f"(c[0]), "+f"(c[1]), "+f"(c[2]), "+f"(c[3])
        : "r"(a[0]), "r"(a[1]), "r"(a[2]), "r"(a[3]), "r"(b[0]), "r"(b[1]));
}
__device__ __forceinline__ void ins3(float v, int i, float* a, int* ai) {
    if (v < a[0] || (v == a[0] && i < ai[0])) {
        a[2] = a[1]; ai[2] = ai[1]; a[1] = a[0]; ai[1] = ai[0]; a[0] = v; ai[0] = i;
    } else if (v < a[1] || (v == a[1] && i < ai[1])) {
        a[2] = a[1]; ai[2] = ai[1]; a[1] = v; ai[1] = i;
    } else if (v < a[2] || (v == a[2] && i < ai[2])) {
        a[2] = v; ai[2] = i;
    }
}

// ---- prep: ||w||^2 ----
__global__ void wsq_kernel(const float* __restrict__ E) {
    int t = blockIdx.x * 256 + threadIdx.x;
    int v = t >> 10, k = t & (NK - 1);
    const float* p = E + (size_t)v * ND * NK + k;
    double s = 0.0;
    #pragma unroll 8
    for (int d = 0; d < ND; ++d) { float w = p[(size_t)d * NK]; s += (double)w * (double)w; }
    g_wsq[t] = (float)s;
    if (t == 0) { g_accum = 0.0; g_fix_count = 0; }
}

// ---- prep: transpose E -> g_Wt fp32 + g_Wh fp16 (fused) ----
__global__ void transpose_kernel(const float* __restrict__ E) {
    __shared__ float t[32][33];
    int v = blockIdx.z, k0 = blockIdx.x * 32, d0 = blockIdx.y * 32;
    int tx = threadIdx.x, ty = threadIdx.y;
    const float* Ev = E + (size_t)v * ND * NK;
    #pragma unroll
    for (int j = 0; j < 32; j += 8) t[ty + j][tx] = Ev[(size_t)(d0 + ty + j) * NK + k0 + tx];
    __syncthreads();
    float* Wv = g_Wt + (size_t)v * NK * ND;
    __half* Hv = g_Wh + (size_t)v * NK * ND;
    #pragma unroll
    for (int j = 0; j < 32; j += 8) {
        float val = t[tx][ty + j];
        size_t o = (size_t)(k0 + ty + j) * ND + d0 + tx;
        Wv[o] = val;
        Hv[o] = __float2half_rn(val);
    }
}

__global__ void convertX_kernel(const float* __restrict__ X) {
    size_t i2 = ((size_t)blockIdx.x * 256 + threadIdx.x) * 2;
    float2 x = *(const float2*)(X + i2);
    *(__half2*)(&g_Xh[i2]) = __floats2half2_rn(x.x, x.y);
}

// ---- exact fp64 score ----
__device__ double dscore(const float* __restrict__ xrow, const float* __restrict__ Ev, int k) {
    const float* wc = Ev + k;
    double dot = 0.0, ws = 0.0;
    #pragma unroll 4
    for (int d = 0; d < ND; ++d) {
        double w = (double)wc[(size_t)d * NK];
        dot += (double)xrow[d] * w;
        ws  += w * w;
    }
    return ws - 2.0 * dot;
}

// ---- main: fp16 HMMA + top-3 + windowed adjudication ----
// grid (NN/128, NV), 256 thr = 8 warps (4M x 2N), warp tile 32x32, 2 CTAs/SM
__global__ void __launch_bounds__(256, 2)
gemm_argmin_kernel(const float* __restrict__ X, const float* __restrict__ E) {
    extern __shared__ char smem[];
    const uint32_t sb = smem_u32(smem);
    const int tid = threadIdx.x, lane = tid & 31, wid = tid >> 5;
    const int wm = wid & 3, wn = wid >> 2;        // 4M x 2N
    const int g = lane >> 2, tg = lane & 3;
    const int v = blockIdx.y, row0 = blockIdx.x * 128;

    {
        float* sw = (float*)(smem + WSQ_S);
        #pragma unroll
        for (int q = 0; q < 4; ++q) sw[tid + q * 256] = g_wsq[v * NK + tid + q * 256];
    }

    const size_t abase = ((size_t)v * NN + row0) * ND;

    // A: all 4 d-tiles resident (one cp.async group)
    {
        #pragma unroll
        for (int j = 0; j < 16; ++j) {
            int q = tid + j * 256;                // 0..4095 16B-chunks
            int dc = q >> 10, r = (q >> 3) & 127, c = q & 7;
            cpa16(sb + AOFF + dc * ATILB + r * ROWB + c * 16,
                  (const char*)g_Xh + (abase + (size_t)r * ND + dc * 64 + c * 8) * 2);
        }
        CP_COMMIT();
    }

    // B issue for phase i (i = nc*4 + dc), ring buffer i % 3
    auto issueB = [&](int i) {
        int nc = i >> 2, dc = i & 3, buf = i % 3;
        size_t bb = ((size_t)v * NK + nc * 64) * ND + dc * 64;
        #pragma unroll
        for (int j = 0; j < 2; ++j) {
            int q = tid * 2 + j;                  // 0..511 16B-chunks
            int r = q >> 3, c = q & 7;
            cpa16(sb + BOFF + buf * BTILB + r * ROWB + c * 16,
                  (const char*)g_Wh + (bb + (size_t)r * ND + c * 8) * 2);
        }
        CP_COMMIT();
    };

    float tv[4][3]; int ti[4][3];
    #pragma unroll
    for (int s = 0; s < 4; ++s)
        #pragma unroll
        for (int j = 0; j < 3; ++j) { tv[s][j] = FLT_MAX; ti[s][j] = 0x7FFFFFFF; }

    issueB(0);
    issueB(1);
    const float* sw = (const float*)(smem + WSQ_S);

    for (int nc = 0; nc < 16; ++nc) {
        float c[2][4][4];
        #pragma unroll
        for (int mf = 0; mf < 2; ++mf)
            #pragma unroll
            for (int nf = 0; nf < 4; ++nf)
                #pragma unroll
                for (int e = 0; e < 4; ++e) c[mf][nf][e] = 0.0f;

        for (int dc = 0; dc < 4; ++dc) {
            int ph = nc * 4 + dc;
            if (ph < 63) { CP_WAIT1(); } else { CP_WAIT0(); }
            __syncthreads();                       // prev phase reads done + this phase data visible
            if (ph < 62) issueB(ph + 2);           // safe: ring slot was consumed 2 phases ago

            const uint32_t Ab = sb + AOFF + dc * ATILB;
            const uint32_t Bb = sb + BOFF + (ph % 3) * BTILB;
            #pragma unroll
            for (int ks = 0; ks < 4; ++ks) {
                const uint32_t kb = ks * 32 + tg * 4;
                uint32_t A[2][4];
                #pragma unroll
                for (int mf = 0; mf < 2; ++mf) {
                    uint32_t ra = Ab + (wm * 32 + mf * 16 + g) * ROWB + kb;
                    A[mf][0] = lds32(ra);       A[mf][1] = lds32(ra + 8 * ROWB);
                    A[mf][2] = lds32(ra + 16);  A[mf][3] = lds32(ra + 8 * ROWB + 16);
                }
                uint32_t B[4][2];
                #pragma unroll
                for (int nf = 0; nf < 4; ++nf) {
                    uint32_t rb = Bb + (wn * 32 + nf * 8 + g) * ROWB + kb;
                    B[nf][0] = lds32(rb); B[nf][1] = lds32(rb + 16);
                }
                #pragma unroll
                for (int mf = 0; mf < 2; ++mf)
                    #pragma unroll
                    for (int nf = 0; nf < 4; ++nf) mma16816(c[mf][nf], A[mf], B[nf]);
            }
        }

        // score this 64-col chunk
        #pragma unroll
        for (int mf = 0; mf < 2; ++mf)
            #pragma unroll
            for (int nf = 0; nf < 4; ++nf)
                #pragma unroll
                for (int e = 0; e < 4; ++e) {
                    int col  = nc * 64 + wn * 32 + nf * 8 + tg * 2 + (e & 1);
                    int slot = mf * 2 + (e >> 1);
                    float sc = sw[col] - 2.0f * c[mf][nf][e];
                    float* a = tv[slot]; int* ai = ti[slot];
                    if (sc < a[2]) {
                        if (sc < a[1]) {
                            a[2] = a[1]; ai[2] = ai[1];
                            if (sc < a[0]) { a[1] = a[0]; ai[1] = ai[0]; a[0] = sc; ai[0] = col; }
                            else           { a[1] = sc; ai[1] = col; }
                        } else { a[2] = sc; ai[2] = col; }
                    }
                }
    }

    // merge top-3 across the 4 lanes sharing each row
    const unsigned m = 0xFFFFFFFFu;
    #pragma unroll
    for (int off = 1; off < 4; off <<= 1) {
        #pragma unroll
        for (int s = 0; s < 4; ++s) {
            float ov[3]; int oi[3];
            #pragma unroll
            for (int j = 0; j < 3; ++j) {
                ov[j] = __shfl_xor_sync(m, tv[s][j], off);
                oi[j] = __shfl_xor_sync(m, ti[s][j], off);
            }
            #pragma unroll
            for (int j = 0; j < 3; ++j) ins3(ov[j], oi[j], tv[s], ti[s]);
        }
    }

    float* mv = (float*)(smem + MRG);          // [2][128][3]
    int*   mi = (int*)  (smem + MRG + 3072);
    __syncthreads();                            // all phases done before merge reuse
    if (tg == 0) {
        #pragma unroll
        for (int s = 0; s < 4; ++s) {
            int rl = wm * 32 + (s >> 1) * 16 + g + (s & 1) * 8;
            #pragma unroll
            for (int j = 0; j < 3; ++j) {
                mv[(wn * 128 + rl) * 3 + j] = tv[s][j];
                mi[(wn * 128 + rl) * 3 + j] = ti[s][j];
            }
        }
    }
    __syncthreads();

    if (tid < 128) {
        float a[3]; int ai[3];
        #pragma unroll
        for (int j = 0; j < 3; ++j) { a[j] = mv[tid * 3 + j]; ai[j] = mi[tid * 3 + j]; }
        #pragma unroll
        for (int j = 0; j < 3; ++j)
            ins3(mv[(128 + tid) * 3 + j], mi[(128 + tid) * 3 + j], a, ai);

        int grow = row0 + tid, kk = ai[0];
        float gap2 = a[1] - a[0], gap3 = a[2] - a[0];
        if (gap3 < W1) {
            int slot = atomicAdd(&g_fix_count, 1);
            g_fix_rows[slot] = v * NN + grow;          // full exact rescore later
        } else if (gap2 < W1) {
            const float* xrow = X + ((size_t)v * NN + grow) * ND;
            const float* Ev = E + (size_t)v * ND * NK;
            double sb2 = dscore(xrow, Ev, ai[0]);
            double ss2 = dscore(xrow, Ev, ai[1]);
            if (ss2 < sb2 || (ss2 == sb2 && ai[1] < ai[0])) kk = ai[1];
        }
        g_idx[v * NN + grow] = kk;
    }
}

// ---- exact full-row rescore for flagged rows ----
__global__ void __launch_bounds__(256)
fix_kernel(const float* __restrict__ X, const float* __restrict__ E) {
    __shared__ float xs[ND];
    __shared__ float wv[16];
    __shared__ int   wi[16];
    int cnt = g_fix_count;
    for (int f = blockIdx.x; f < cnt; f += gridDim.x) {
        int R = g_fix_rows[f];
        int v = R >> 13;
        __syncthreads();
        xs[threadIdx.x] = X[(size_t)R * ND + threadIdx.x];
        __syncthreads();

        float b = FLT_MAX, s = FLT_MAX; int bi = 0x7FFFFFFF, si = 0x7FFFFFFF;
        #pragma unroll
        for (int kk = 0; kk < 4; ++kk) {
            int k = threadIdx.x * 4 + kk;
            const float* w = g_Wt + ((size_t)v * NK + k) * ND;
            float dot = 0.0f;
            #pragma unroll 8
            for (int d = 0; d < ND; ++d) dot = fmaf(xs[d], w[d], dot);
            float sc = g_wsq[v * NK + k] - 2.0f * dot;
            if (sc < b || (sc == b && k < bi)) { s = b; si = bi; b = sc; bi = k; }
            else if (sc < s || (sc == s && k < si)) { s = sc; si = k; }
        }
        const unsigned m = 0xFFFFFFFFu;
        #pragma unroll
        for (int off = 1; off < 32; off <<= 1) {
            float ob = __shfl_xor_sync(m, b, off);  int obi = __shfl_xor_sync(m, bi, off);
            float os = __shfl_xor_sync(m, s, off);  int osi = __shfl_xor_sync(m, si, off);
            bool tko = (ob < b) || (ob == b && obi < bi);
            float lb = tko ? b : ob; int lbi = tko ? bi : obi;
            float ws_ = tko ? os : s; int wsi = tko ? osi : si;
            if (tko) { b = ob; bi = obi; }
            if (ws_ < lb || (ws_ == lb && wsi < lbi)) { s = ws_; si = wsi; }
            else                                      { s = lb;  si = lbi; }
        }
        int wrp = threadIdx.x >> 5;
        if ((threadIdx.x & 31) == 0) { wv[wrp * 2] = b; wv[wrp * 2 + 1] = s; wi[wrp * 2] = bi; wi[wrp * 2 + 1] = si; }
        __syncthreads();
        if (threadIdx.x == 0) {
            float B = FLT_MAX, S = FLT_MAX; int Bi = 0x7FFFFFFF, Si = 0x7FFFFFFF;
            for (int q = 0; q < 16; ++q) {
                float vq = wv[q]; int iq = wi[q];
                if (vq < B || (vq == B && iq < Bi)) { S = B; Si = Bi; B = vq; Bi = iq; }
                else if (vq < S || (vq == S && iq < Si)) { S = vq; Si = iq; }
            }
            int kk = Bi;
            if (S - B < MARGIN) {
                const float* Ev = E + (size_t)v * ND * NK;
                double sb2 = dscore(xs, Ev, Bi);
                double ss2 = dscore(xs, Ev, Si);
                if (ss2 < sb2 || (ss2 == sb2 && Si < Bi)) kk = Si;
            }
            g_idx[R] = kk;
        }
        __syncthreads();
    }
}

// ---- gather + loss ----
__global__ void __launch_bounds__(256)
gather_kernel(const float* __restrict__ X, float* __restrict__ out) {
    int R = blockIdx.x * 4 + (threadIdx.x >> 6);
    int lane64 = threadIdx.x & 63;
    int k = g_idx[R];
    int v = R >> 13;
    float4 qv = ((const float4*)(g_Wt + ((size_t)v * NK + k) * ND))[lane64];
    float4 xv = ((const float4*)(X + (size_t)R * ND))[lane64];
    ((float4*)(out + (size_t)R * ND))[lane64] = qv;

    float dx = qv.x - xv.x, dy = qv.y - xv.y, dz = qv.z - xv.z, dw = qv.w - xv.w;
    float s = dx * dx + dy * dy + dz * dz + dw * dw;
    #pragma unroll
    for (int off = 16; off > 0; off >>= 1) s += __shfl_down_sync(0xFFFFFFFFu, s, off);

    __shared__ float ps[8];
    int w = threadIdx.x >> 5, l = threadIdx.x & 31;
    if (l == 0) ps[w] = s;
    __syncthreads();
    if (threadIdx.x == 0) {
        float tot = 0.0f;
        #pragma unroll
        for (int i = 0; i < 8; ++i) tot += ps[i];
        atomicAdd(&g_accum, (double)tot);
    }
}

__global__ void loss_kernel(float* __restrict__ out, long long out_size) {
    const long long VND = (long long)NV * NN * ND;
    double loss = 1.25 * g_accum / (double)VND;
    for (long long i = VND + threadIdx.x; i < out_size; i += blockDim.x)
        out[i] = (float)loss;
}

extern "C" void kernel_launch(void* const* d_in, const int* in_sizes, int n_in,
                              void* d_out, int out_size) {
    const float* X = (const float*)d_in[0];
    const float* E = (const float*)d_in[1];
    float* out = (float*)d_out;

    cudaFuncSetAttribute((const void*)gemm_argmin_kernel,
                         cudaFuncAttributeMaxDynamicSharedMemorySize, SMEM_TOTAL);

    wsq_kernel<<<64, 256>>>(E);
    transpose_kernel<<<dim3(NK / 32, ND / 32, NV), dim3(32, 8)>>>(E);
    convertX_kernel<<<65536, 256>>>(X);
    gemm_argmin_kernel<<<dim3(NN / 128, NV), 256, SMEM_TOTAL>>>(X, E);
    fix_kernel<<<1024, 256>>>(X, E);
    gather_kernel<<<(NV * NN) / 4, 256>>>(X, out);
    loss_kernel<<<1, 32>>>(out, (long long)out_size);
}